// round 15
// baseline (speedup 1.0000x reference)
#include <cuda_runtime.h>
#include <math.h>
#include <float.h>
#include <stdint.h>

// ---------------- problem constants ----------------
#define C_H      768
#define C_IDXD   64
#define C_K      10
#define C_R      12
#define C_READK  100
#define C_MD     64
#define C_WK     100
#define C_INTER  3072
#define C_N      50000
#define C_B      4
#define C_E      128
#define C_BE     512          // B*E
#define C_DEPTH  4
#define C_SLOTS  110          // K + READ_K
#define C_PAIRS  1000         // K*WK
#define C_PAD    1024
#define PAD_COL  0x7FFFFFFF

// ---------------- device scratch (no allocations allowed) ----------------
__device__ float g_qidx[C_BE * 256];          // indexer queries
__device__ float g_qh  [C_BE * C_H];          // mha queries
__device__ int   g_ei  [C_BE * C_K];          // e2n indices
__device__ float g_ev  [C_BE * C_K];          // e2n values
__device__ float g_attd[C_BE * C_H];          // attention output (R*MD)
__device__ float g_h1  [C_BE * C_INTER];      // FFN intermediate
__device__ float g_h2  [C_BE * C_H];          // FFN output pre-LN
__device__ float g_loss;

__global__ void k_init() { g_loss = 0.0f; }

// ---------------- generic tiled SGEMM: C = A(MxK) @ B(KxN) + bias, opt gelu ----------------
__global__ __launch_bounds__(256) void sgemm_bias(
    const float* __restrict__ A, const float* __restrict__ B,
    const float* __restrict__ bias, float* __restrict__ C,
    int M, int N, int Kd, int act)
{
    __shared__ float As[16][64];
    __shared__ float Bs[16][64];
    const int bm = blockIdx.y * 64;
    const int bn = blockIdx.x * 64;
    const int tid = threadIdx.x;
    const int tm = (tid >> 4) << 2;   // 0..60
    const int tn = (tid & 15) << 2;   // 0..60
    float acc[4][4];
#pragma unroll
    for (int i = 0; i < 4; i++)
#pragma unroll
        for (int j = 0; j < 4; j++) acc[i][j] = 0.0f;

    for (int k0 = 0; k0 < Kd; k0 += 16) {
#pragma unroll
        for (int i = 0; i < 4; i++) {
            int idx = tid + i * 256;
            int m  = idx >> 4, ka = idx & 15;
            As[ka][m] = A[(size_t)(bm + m) * Kd + k0 + ka];
            int kb = idx >> 6, n = idx & 63;
            Bs[kb][n] = B[(size_t)(k0 + kb) * N + bn + n];
        }
        __syncthreads();
#pragma unroll
        for (int kk = 0; kk < 16; kk++) {
            float4 a4 = *(const float4*)&As[kk][tm];
            float4 b4 = *(const float4*)&Bs[kk][tn];
            float av[4] = {a4.x, a4.y, a4.z, a4.w};
            float bv[4] = {b4.x, b4.y, b4.z, b4.w};
#pragma unroll
            for (int i = 0; i < 4; i++)
#pragma unroll
                for (int j = 0; j < 4; j++) acc[i][j] = fmaf(av[i], bv[j], acc[i][j]);
        }
        __syncthreads();
    }
#pragma unroll
    for (int i = 0; i < 4; i++) {
#pragma unroll
        for (int j = 0; j < 4; j++) {
            float v = acc[i][j] + bias[bn + tn + j];
            if (act) v = 0.5f * v * (1.0f + erff(v * 0.70710678118654752f)); // exact gelu
            C[(size_t)(bm + tm + i) * N + bn + tn + j] = v;
        }
    }
}

// ---------------- hierarchical product-key indexer ----------------
__global__ __launch_bounds__(128) void k_indexer(
    const float* __restrict__ key0, const float* __restrict__ key1,
    const float* __restrict__ key2, const float* __restrict__ key3)
{
    const int row = blockIdx.x;
    const int tid = threadIdx.x;
    __shared__ float sq[256];
    __shared__ float sc[128];
    __shared__ int   s_ind[10];
    __shared__ float s_val[10];

    for (int t = tid; t < 256; t += 128) sq[t] = g_qidx[(size_t)row * 256 + t];
    __syncthreads();

    // level 0: softmax over 100 keys, top-10 (softmax denominators cancel after renorm)
    for (int n = tid; n < 100; n += 128) {
        const float* kp = key0 + (size_t)n * 64;
        float d = 0.0f;
        for (int q = 0; q < 64; q++) d = fmaf(sq[q], kp[q], d);
        sc[n] = d * 0.125f;
    }
    __syncthreads();
    if (tid == 0) {
        float raw[10]; int idx[10];
        for (int it = 0; it < 10; it++) {
            float bm = -FLT_MAX; int bi = 0;
            for (int n = 0; n < 100; n++) if (sc[n] > bm) { bm = sc[n]; bi = n; }
            raw[it] = bm; idx[it] = bi; sc[bi] = -FLT_MAX;
        }
        float m = raw[0], z = 0.0f;
        for (int it = 0; it < 10; it++) z += expf(raw[it] - m);
        for (int it = 0; it < 10; it++) { s_ind[it] = idx[it]; s_val[it] = expf(raw[it] - m) / z; }
    }
    __syncthreads();

    const float* keys[3] = {key1, key2, key3};
    const int branches[3] = {10, 10, 5};
    for (int lvl = 0; lvl < 3; lvl++) {
        const int bi = branches[lvl];
        const int cnt = 10 * bi;
        const float* KY = keys[lvl];
        const float* qv = sq + (lvl + 1) * 64;
        for (int t = tid; t < cnt; t += 128) {
            int k = t / bi, c = t - k * bi;
            const float* kp = KY + ((size_t)s_ind[k] * bi + c) * 64;
            float d = 0.0f;
            for (int q = 0; q < 64; q++) d = fmaf(qv[q], kp[q], d);
            sc[t] = d * 0.125f;
        }
        __syncthreads();
        if (tid < 10) { // per-parent softmax, scale by parent weight
            float m = -FLT_MAX;
            for (int c = 0; c < bi; c++) m = fmaxf(m, sc[tid * bi + c]);
            float z = 0.0f;
            for (int c = 0; c < bi; c++) z += expf(sc[tid * bi + c] - m);
            float inv = s_val[tid] / z;
            for (int c = 0; c < bi; c++) sc[tid * bi + c] = inv * expf(sc[tid * bi + c] - m);
        }
        __syncthreads();
        if (tid == 0) {
            int ni[10]; float nv[10]; float vs = 0.0f;
            for (int it = 0; it < 10; it++) {
                float bmv = -FLT_MAX; int bix = 0;
                for (int t = 0; t < cnt; t++) if (sc[t] > bmv) { bmv = sc[t]; bix = t; }
                sc[bix] = -FLT_MAX;
                ni[it] = s_ind[bix / bi] * bi + bix % bi;
                nv[it] = bmv; vs += bmv;
            }
            for (int it = 0; it < 10; it++) { s_ind[it] = ni[it]; s_val[it] = nv[it] / vs; }
        }
        __syncthreads();
    }
    if (tid < 10) {
        g_ei[row * C_K + tid] = s_ind[tid];
        g_ev[row * C_K + tid] = s_val[tid];
    }
}

// ---------------- fused per-(row, r) sparse block ----------------
// gather wiring -> sort by col -> coalesce -> e222e + loss -> top-100 -> attention
__global__ __launch_bounds__(256) void k_main(
    const int*   __restrict__ wedges,
    const float* __restrict__ wweights,
    const float* __restrict__ mvals,
    const float* __restrict__ e2e)
{
    const int row = blockIdx.x;
    const int r   = blockIdx.y;
    const int tid = threadIdx.x;
    const int b   = row >> 7;
    const int i   = row & 127;

    __shared__ int   s_col[C_PAD];
    __shared__ float s_vv [C_PAD];
    __shared__ int   u_col[C_PAD];
    __shared__ float u_val[C_PAD];
    __shared__ int   s_cnt[257];
    __shared__ float s_red[256];
    __shared__ int   my_ind[10];
    __shared__ float my_val[10];
    __shared__ int   s_slot[C_SLOTS];
    __shared__ float s_sc  [C_SLOTS];
    __shared__ float s_q[64];
    __shared__ float s_mz[2];

    if (tid < 10) { my_ind[tid] = g_ei[row * C_K + tid]; my_val[tid] = g_ev[row * C_K + tid]; }
    if (tid < 64) s_q[tid] = g_qh[(size_t)row * C_H + r * 64 + tid];
    __syncthreads();

    // ---- Phase A: gather candidate (col, val) pairs ----
    for (int t = tid; t < C_PAD; t += 256) {
        if (t < C_PAIRS) {
            int k = t / 100, w = t - k * 100;
            size_t base = ((size_t)r * C_N + my_ind[k]) * C_WK + w;
            s_col[t] = wedges[base];
            s_vv[t]  = my_val[k] * wweights[base];
        } else { s_col[t] = PAD_COL; s_vv[t] = 0.0f; }
    }
    __syncthreads();

    // ---- bitonic sort ascending by col ----
    for (int ks = 2; ks <= C_PAD; ks <<= 1)
        for (int j = ks >> 1; j > 0; j >>= 1) {
            for (int t = tid; t < C_PAD; t += 256) {
                int ix = t ^ j;
                if (ix > t) {
                    bool up = ((t & ks) == 0);
                    int a = s_col[t], c = s_col[ix];
                    if ((a > c) == up) {
                        s_col[t] = c; s_col[ix] = a;
                        float tv = s_vv[t]; s_vv[t] = s_vv[ix]; s_vv[ix] = tv;
                    }
                }
            }
            __syncthreads();
        }

    // ---- coalesce duplicates into u_col/u_val ----
    {
        int base4 = tid * 4, cnt = 0;
        for (int o = 0; o < 4; o++) {
            int idx = base4 + o, c = s_col[idx];
            if (c != PAD_COL && (idx == 0 || s_col[idx - 1] != c)) cnt++;
        }
        s_cnt[tid] = cnt;
    }
    __syncthreads();
    if (tid == 0) {
        int run = 0;
        for (int t = 0; t < 256; t++) { int c = s_cnt[t]; s_cnt[t] = run; run += c; }
        s_cnt[256] = run;
    }
    __syncthreads();
    {
        int pos = s_cnt[tid], base4 = tid * 4;
        for (int o = 0; o < 4; o++) {
            int idx = base4 + o, c = s_col[idx];
            if (c != PAD_COL && (idx == 0 || s_col[idx - 1] != c)) {
                float v = s_vv[idx];
                for (int j2 = idx + 1; j2 < C_PAD && s_col[j2] == c; j2++) v += s_vv[j2];
                u_col[pos] = c; u_val[pos] = v; pos++;
            }
        }
    }
    __syncthreads();
    const int U = s_cnt[256];

    // ---- Phase B: e222e row + write-loss (binary search in coalesced list) ----
    float lsum = 0.0f;
    {
        const int*   ei  = g_ei + (size_t)(b * C_E) * C_K;
        const float* ev  = g_ev + (size_t)(b * C_E) * C_K;
        const float* tgt = e2e + (((size_t)b * C_R + r) * C_E + i) * C_E;
        for (int j = tid; j < C_E; j += 256) {
            float acc = 0.0f;
#pragma unroll
            for (int k = 0; k < 10; k++) {
                int key = ei[j * C_K + k];
                int lo = 0, hi = U;
                while (lo < hi) { int mid = (lo + hi) >> 1; if (u_col[mid] < key) lo = mid + 1; else hi = mid; }
                if (lo < U && u_col[lo] == key) acc = fmaf(ev[j * C_K + k], u_val[lo], acc);
            }
            float d = acc - tgt[j];
            lsum = fmaf(d, d, lsum);
        }
    }
    s_red[tid] = lsum;
    __syncthreads();
    for (int s = 128; s > 0; s >>= 1) { if (tid < s) s_red[tid] += s_red[tid + s]; __syncthreads(); }
    if (tid == 0) atomicAdd(&g_loss, s_red[0] * (1.0f / (C_B * C_E * C_E)));

    // ---- Phase C: top READ_K by value (bitonic descending) ----
    for (int t = tid; t < C_PAD; t += 256) if (t >= U) u_val[t] = -FLT_MAX;
    __syncthreads();
    for (int ks = 2; ks <= C_PAD; ks <<= 1)
        for (int j = ks >> 1; j > 0; j >>= 1) {
            for (int t = tid; t < C_PAD; t += 256) {
                int ix = t ^ j;
                if (ix > t) {
                    bool up = ((t & ks) == 0);
                    float a = u_val[t], c = u_val[ix];
                    if ((a < c) == up) {           // descending
                        u_val[t] = c; u_val[ix] = a;
                        int tc = u_col[t]; u_col[t] = u_col[ix]; u_col[ix] = tc;
                    }
                }
            }
            __syncthreads();
        }
    if (tid < C_SLOTS) s_slot[tid] = (tid < C_K) ? my_ind[tid] : u_col[tid - C_K];
    __syncthreads();

    // ---- Phase D: attention over 110 memory_values slots ----
    const float* MV = mvals + (size_t)r * C_N * 64;
    {
        int warp = tid >> 5, lane = tid & 31;
        for (int s = warp; s < C_SLOTS; s += 8) {
            const float* v = MV + (size_t)s_slot[s] * 64;
            float p = fmaf(v[lane], s_q[lane], v[lane + 32] * s_q[lane + 32]);
#pragma unroll
            for (int o = 16; o > 0; o >>= 1) p += __shfl_down_sync(0xffffffffu, p, o);
            if (lane == 0) s_sc[s] = p * 0.125f;
        }
    }
    __syncthreads();
    if (tid == 0) {
        float m = -FLT_MAX;
        for (int s = 0; s < C_SLOTS; s++) m = fmaxf(m, s_sc[s]);
        s_mz[0] = m;
    }
    __syncthreads();
    if (tid < C_SLOTS) s_sc[tid] = expf(s_sc[tid] - s_mz[0]);
    __syncthreads();
    if (tid == 0) {
        float z = 0.0f;
        for (int s = 0; s < C_SLOTS; s++) z += s_sc[s];
        s_mz[1] = 1.0f / z;
    }
    __syncthreads();
    {
        int g = tid >> 6, d = tid & 63;
        float p = 0.0f;
        for (int s = g; s < C_SLOTS; s += 4) p = fmaf(s_sc[s], MV[(size_t)s_slot[s] * 64 + d], p);
        s_red[tid] = p;
        __syncthreads();
        if (tid < 64) {
            float o = (s_red[tid] + s_red[tid + 64] + s_red[tid + 128] + s_red[tid + 192]) * s_mz[1];
            g_attd[(size_t)row * C_H + r * 64 + tid] = o;
        }
    }
}

// ---------------- layernorm + output + loss write ----------------
__global__ __launch_bounds__(256) void k_ln(
    const float* __restrict__ lng, const float* __restrict__ lnb, float* __restrict__ out)
{
    const int row = blockIdx.x;
    const int tid = threadIdx.x;
    __shared__ float s_red[256];
    __shared__ float s_mu, s_rs;
    const float* h = g_h2 + (size_t)row * C_H;
    float h0 = h[tid], h1 = h[tid + 256], h2 = h[tid + 512];
    s_red[tid] = h0 + h1 + h2;
    __syncthreads();
    for (int s = 128; s > 0; s >>= 1) { if (tid < s) s_red[tid] += s_red[tid + s]; __syncthreads(); }
    if (tid == 0) s_mu = s_red[0] * (1.0f / C_H);
    __syncthreads();
    float mu = s_mu;
    float d0 = h0 - mu, d1 = h1 - mu, d2 = h2 - mu;
    s_red[tid] = d0 * d0 + d1 * d1 + d2 * d2;
    __syncthreads();
    for (int s = 128; s > 0; s >>= 1) { if (tid < s) s_red[tid] += s_red[tid + s]; __syncthreads(); }
    if (tid == 0) s_rs = rsqrtf(s_red[0] * (1.0f / C_H) + 1e-5f);
    __syncthreads();
    float rs = s_rs;
    out[(size_t)row * C_H + tid]       = d0 * rs * lng[tid]       + lnb[tid];
    out[(size_t)row * C_H + tid + 256] = d1 * rs * lng[tid + 256] + lnb[tid + 256];
    out[(size_t)row * C_H + tid + 512] = d2 * rs * lng[tid + 512] + lnb[tid + 512];
    if (row == 0 && tid == 0) out[(size_t)C_BE * C_H] = g_loss;
}

// ---------------- host launch ----------------
extern "C" void kernel_launch(void* const* d_in, const int* in_sizes, int n_in,
                              void* d_out, int out_size)
{
    (void)in_sizes; (void)n_in; (void)out_size;
    const float* elem_hiddens = (const float*)d_in[0];
    const float* e2e          = (const float*)d_in[1];
    const float* Wq_idx       = (const float*)d_in[2];
    const float* bq_idx       = (const float*)d_in[3];
    const float* key0         = (const float*)d_in[4];
    const float* key1         = (const float*)d_in[5];
    const float* key2         = (const float*)d_in[6];
    const float* key3         = (const float*)d_in[7];
    // d_in[8] = memory_keys: dead code in reference (attention scores against VALUES)
    const float* mvals        = (const float*)d_in[9];
    const float* wweights     = (const float*)d_in[10];
    const float* Wq_mha       = (const float*)d_in[11];
    const float* bq_mha       = (const float*)d_in[12];
    const float* W1           = (const float*)d_in[13];
    const float* b1           = (const float*)d_in[14];
    const float* W2           = (const float*)d_in[15];
    const float* b2           = (const float*)d_in[16];
    const float* ln_g         = (const float*)d_in[17];
    const float* ln_b         = (const float*)d_in[18];
    const int*   wedges       = (const int*)d_in[19];
    float* out = (float*)d_out;

    float *p_qidx, *p_qh, *p_attd, *p_h1, *p_h2;
    cudaGetSymbolAddress((void**)&p_qidx, g_qidx);
    cudaGetSymbolAddress((void**)&p_qh,   g_qh);
    cudaGetSymbolAddress((void**)&p_attd, g_attd);
    cudaGetSymbolAddress((void**)&p_h1,   g_h1);
    cudaGetSymbolAddress((void**)&p_h2,   g_h2);

    k_init<<<1, 1>>>();
    // indexer queries: (512x768) @ (768x256) + bq_idx
    sgemm_bias<<<dim3(256 / 64, C_BE / 64), 256>>>(elem_hiddens, Wq_idx, bq_idx, p_qidx, C_BE, 256, C_H, 0);
    // mha queries: (512x768) @ (768x768) + bq_mha
    sgemm_bias<<<dim3(C_H / 64, C_BE / 64), 256>>>(elem_hiddens, Wq_mha, bq_mha, p_qh, C_BE, C_H, C_H, 0);
    // product-key top-k retrieval
    k_indexer<<<C_BE, 128>>>(key0, key1, key2, key3);
    // fused sparse block per (row, r)
    k_main<<<dim3(C_BE, C_R), 256>>>(wedges, wweights, mvals, e2e);
    // FFN
    sgemm_bias<<<dim3(C_INTER / 64, C_BE / 64), 256>>>(p_attd, W1, b1, p_h1, C_BE, C_INTER, C_H, 1);
    sgemm_bias<<<dim3(C_H / 64, C_BE / 64), 256>>>(p_h1, W2, b2, p_h2, C_BE, C_H, C_INTER, 0);
    // layernorm + write output + loss scalar
    k_ln<<<C_BE, 256>>>(ln_g, ln_b, out);
}

// round 16
// speedup vs baseline: 1.0035x; 1.0035x over previous
#include <cuda_runtime.h>
#include <math.h>
#include <float.h>
#include <stdint.h>

// ---------------- problem constants ----------------
#define C_H      768
#define C_IDXD   64
#define C_K      10
#define C_R      12
#define C_READK  100
#define C_MD     64
#define C_WK     100
#define C_INTER  3072
#define C_N      50000
#define C_B      4
#define C_E      128
#define C_BE     512          // B*E
#define C_DEPTH  4
#define C_SLOTS  110          // K + READ_K
#define C_PAIRS  1000         // K*WK
#define C_PAD    1024
#define PAD_COL  0x7FFFFFFF

// ---------------- device scratch (no allocations allowed) ----------------
__device__ float g_qidx[C_BE * 256];          // indexer queries
__device__ float g_qh  [C_BE * C_H];          // mha queries
__device__ int   g_ei  [C_BE * C_K];          // e2n indices
__device__ float g_ev  [C_BE * C_K];          // e2n values
__device__ float g_attd[C_BE * C_H];          // attention output (R*MD)
__device__ float g_h1  [C_BE * C_INTER];      // FFN intermediate
__device__ float g_h2  [C_BE * C_H];          // FFN output pre-LN
__device__ float g_loss;

__global__ void k_init() { g_loss = 0.0f; }

// ---------------- generic tiled SGEMM: C = A(MxK) @ B(KxN) + bias, opt gelu ----------------
__global__ __launch_bounds__(256) void sgemm_bias(
    const float* __restrict__ A, const float* __restrict__ B,
    const float* __restrict__ bias, float* __restrict__ C,
    int M, int N, int Kd, int act)
{
    __shared__ float As[16][64];
    __shared__ float Bs[16][64];
    const int bm = blockIdx.y * 64;
    const int bn = blockIdx.x * 64;
    const int tid = threadIdx.x;
    const int tm = (tid >> 4) << 2;   // 0..60
    const int tn = (tid & 15) << 2;   // 0..60
    float acc[4][4];
#pragma unroll
    for (int i = 0; i < 4; i++)
#pragma unroll
        for (int j = 0; j < 4; j++) acc[i][j] = 0.0f;

    for (int k0 = 0; k0 < Kd; k0 += 16) {
#pragma unroll
        for (int i = 0; i < 4; i++) {
            int idx = tid + i * 256;
            int m  = idx >> 4, ka = idx & 15;
            As[ka][m] = A[(size_t)(bm + m) * Kd + k0 + ka];
            int kb = idx >> 6, n = idx & 63;
            Bs[kb][n] = B[(size_t)(k0 + kb) * N + bn + n];
        }
        __syncthreads();
#pragma unroll
        for (int kk = 0; kk < 16; kk++) {
            float4 a4 = *(const float4*)&As[kk][tm];
            float4 b4 = *(const float4*)&Bs[kk][tn];
            float av[4] = {a4.x, a4.y, a4.z, a4.w};
            float bv[4] = {b4.x, b4.y, b4.z, b4.w};
#pragma unroll
            for (int i = 0; i < 4; i++)
#pragma unroll
                for (int j = 0; j < 4; j++) acc[i][j] = fmaf(av[i], bv[j], acc[i][j]);
        }
        __syncthreads();
    }
#pragma unroll
    for (int i = 0; i < 4; i++) {
#pragma unroll
        for (int j = 0; j < 4; j++) {
            float v = acc[i][j] + bias[bn + tn + j];
            if (act) v = 0.5f * v * (1.0f + erff(v * 0.70710678118654752f)); // exact gelu
            C[(size_t)(bm + tm + i) * N + bn + tn + j] = v;
        }
    }
}

// ---------------- hierarchical product-key indexer ----------------
__global__ __launch_bounds__(128) void k_indexer(
    const float* __restrict__ key0, const float* __restrict__ key1,
    const float* __restrict__ key2, const float* __restrict__ key3)
{
    const int row = blockIdx.x;
    const int tid = threadIdx.x;
    __shared__ float sq[256];
    __shared__ float sc[128];
    __shared__ int   s_ind[10];
    __shared__ float s_val[10];

    for (int t = tid; t < 256; t += 128) sq[t] = g_qidx[(size_t)row * 256 + t];
    __syncthreads();

    // level 0: softmax over 100 keys, top-10 (softmax denominators cancel after renorm)
    for (int n = tid; n < 100; n += 128) {
        const float* kp = key0 + (size_t)n * 64;
        float d = 0.0f;
        for (int q = 0; q < 64; q++) d = fmaf(sq[q], kp[q], d);
        sc[n] = d * 0.125f;
    }
    __syncthreads();
    if (tid == 0) {
        float raw[10]; int idx[10];
        for (int it = 0; it < 10; it++) {
            float bm = -FLT_MAX; int bi = 0;
            for (int n = 0; n < 100; n++) if (sc[n] > bm) { bm = sc[n]; bi = n; }
            raw[it] = bm; idx[it] = bi; sc[bi] = -FLT_MAX;
        }
        float m = raw[0], z = 0.0f;
        for (int it = 0; it < 10; it++) z += expf(raw[it] - m);
        for (int it = 0; it < 10; it++) { s_ind[it] = idx[it]; s_val[it] = expf(raw[it] - m) / z; }
    }
    __syncthreads();

    const float* keys[3] = {key1, key2, key3};
    const int branches[3] = {10, 10, 5};
    for (int lvl = 0; lvl < 3; lvl++) {
        const int bi = branches[lvl];
        const int cnt = 10 * bi;
        const float* KY = keys[lvl];
        const float* qv = sq + (lvl + 1) * 64;
        for (int t = tid; t < cnt; t += 128) {
            int k = t / bi, c = t - k * bi;
            const float* kp = KY + ((size_t)s_ind[k] * bi + c) * 64;
            float d = 0.0f;
            for (int q = 0; q < 64; q++) d = fmaf(qv[q], kp[q], d);
            sc[t] = d * 0.125f;
        }
        __syncthreads();
        if (tid < 10) { // per-parent softmax, scale by parent weight
            float m = -FLT_MAX;
            for (int c = 0; c < bi; c++) m = fmaxf(m, sc[tid * bi + c]);
            float z = 0.0f;
            for (int c = 0; c < bi; c++) z += expf(sc[tid * bi + c] - m);
            float inv = s_val[tid] / z;
            for (int c = 0; c < bi; c++) sc[tid * bi + c] = inv * expf(sc[tid * bi + c] - m);
        }
        __syncthreads();
        if (tid == 0) {
            int ni[10]; float nv[10]; float vs = 0.0f;
            for (int it = 0; it < 10; it++) {
                float bmv = -FLT_MAX; int bix = 0;
                for (int t = 0; t < cnt; t++) if (sc[t] > bmv) { bmv = sc[t]; bix = t; }
                sc[bix] = -FLT_MAX;
                ni[it] = s_ind[bix / bi] * bi + bix % bi;
                nv[it] = bmv; vs += bmv;
            }
            for (int it = 0; it < 10; it++) { s_ind[it] = ni[it]; s_val[it] = nv[it] / vs; }
        }
        __syncthreads();
    }
    if (tid < 10) {
        g_ei[row * C_K + tid] = s_ind[tid];
        g_ev[row * C_K + tid] = s_val[tid];
    }
}

// ---------------- fused per-(row, r) sparse block ----------------
// gather wiring -> sort by col -> coalesce -> e222e + loss -> top-100 -> attention
__global__ __launch_bounds__(256) void k_main(
    const int*   __restrict__ wedges,
    const float* __restrict__ wweights,
    const float* __restrict__ mvals,
    const float* __restrict__ e2e)
{
    const int row = blockIdx.x;
    const int r   = blockIdx.y;
    const int tid = threadIdx.x;
    const int b   = row >> 7;
    const int i   = row & 127;

    __shared__ int   s_col[C_PAD];
    __shared__ float s_vv [C_PAD];
    __shared__ int   u_col[C_PAD];
    __shared__ float u_val[C_PAD];
    __shared__ int   s_cnt[257];
    __shared__ float s_red[256];
    __shared__ int   my_ind[10];
    __shared__ float my_val[10];
    __shared__ int   s_slot[C_SLOTS];
    __shared__ float s_sc  [C_SLOTS];
    __shared__ float s_q[64];
    __shared__ float s_mz[2];

    if (tid < 10) { my_ind[tid] = g_ei[row * C_K + tid]; my_val[tid] = g_ev[row * C_K + tid]; }
    if (tid < 64) s_q[tid] = g_qh[(size_t)row * C_H + r * 64 + tid];
    __syncthreads();

    // ---- Phase A: gather candidate (col, val) pairs ----
    for (int t = tid; t < C_PAD; t += 256) {
        if (t < C_PAIRS) {
            int k = t / 100, w = t - k * 100;
            size_t base = ((size_t)r * C_N + my_ind[k]) * C_WK + w;
            s_col[t] = wedges[base];
            s_vv[t]  = my_val[k] * wweights[base];
        } else { s_col[t] = PAD_COL; s_vv[t] = 0.0f; }
    }
    __syncthreads();

    // ---- bitonic sort ascending by col ----
    for (int ks = 2; ks <= C_PAD; ks <<= 1)
        for (int j = ks >> 1; j > 0; j >>= 1) {
            for (int t = tid; t < C_PAD; t += 256) {
                int ix = t ^ j;
                if (ix > t) {
                    bool up = ((t & ks) == 0);
                    int a = s_col[t], c = s_col[ix];
                    if ((a > c) == up) {
                        s_col[t] = c; s_col[ix] = a;
                        float tv = s_vv[t]; s_vv[t] = s_vv[ix]; s_vv[ix] = tv;
                    }
                }
            }
            __syncthreads();
        }

    // ---- coalesce duplicates into u_col/u_val ----
    {
        int base4 = tid * 4, cnt = 0;
        for (int o = 0; o < 4; o++) {
            int idx = base4 + o, c = s_col[idx];
            if (c != PAD_COL && (idx == 0 || s_col[idx - 1] != c)) cnt++;
        }
        s_cnt[tid] = cnt;
    }
    __syncthreads();
    if (tid == 0) {
        int run = 0;
        for (int t = 0; t < 256; t++) { int c = s_cnt[t]; s_cnt[t] = run; run += c; }
        s_cnt[256] = run;
    }
    __syncthreads();
    {
        int pos = s_cnt[tid], base4 = tid * 4;
        for (int o = 0; o < 4; o++) {
            int idx = base4 + o, c = s_col[idx];
            if (c != PAD_COL && (idx == 0 || s_col[idx - 1] != c)) {
                float v = s_vv[idx];
                for (int j2 = idx + 1; j2 < C_PAD && s_col[j2] == c; j2++) v += s_vv[j2];
                u_col[pos] = c; u_val[pos] = v; pos++;
            }
        }
    }
    __syncthreads();
    const int U = s_cnt[256];

    // ---- Phase B: e222e row + write-loss (binary search in coalesced list) ----
    float lsum = 0.0f;
    {
        const int*   ei  = g_ei + (size_t)(b * C_E) * C_K;
        const float* ev  = g_ev + (size_t)(b * C_E) * C_K;
        const float* tgt = e2e + (((size_t)b * C_R + r) * C_E + i) * C_E;
        for (int j = tid; j < C_E; j += 256) {
            float acc = 0.0f;
#pragma unroll
            for (int k = 0; k < 10; k++) {
                int key = ei[j * C_K + k];
                int lo = 0, hi = U;
                while (lo < hi) { int mid = (lo + hi) >> 1; if (u_col[mid] < key) lo = mid + 1; else hi = mid; }
                if (lo < U && u_col[lo] == key) acc = fmaf(ev[j * C_K + k], u_val[lo], acc);
            }
            float d = acc - tgt[j];
            lsum = fmaf(d, d, lsum);
        }
    }
    s_red[tid] = lsum;
    __syncthreads();
    for (int s = 128; s > 0; s >>= 1) { if (tid < s) s_red[tid] += s_red[tid + s]; __syncthreads(); }
    if (tid == 0) atomicAdd(&g_loss, s_red[0] * (1.0f / (C_B * C_E * C_E)));

    // ---- Phase C: top READ_K by value (bitonic descending) ----
    for (int t = tid; t < C_PAD; t += 256) if (t >= U) u_val[t] = -FLT_MAX;
    __syncthreads();
    for (int ks = 2; ks <= C_PAD; ks <<= 1)
        for (int j = ks >> 1; j > 0; j >>= 1) {
            for (int t = tid; t < C_PAD; t += 256) {
                int ix = t ^ j;
                if (ix > t) {
                    bool up = ((t & ks) == 0);
                    float a = u_val[t], c = u_val[ix];
                    if ((a < c) == up) {           // descending
                        u_val[t] = c; u_val[ix] = a;
                        int tc = u_col[t]; u_col[t] = u_col[ix]; u_col[ix] = tc;
                    }
                }
            }
            __syncthreads();
        }
    if (tid < C_SLOTS) s_slot[tid] = (tid < C_K) ? my_ind[tid] : u_col[tid - C_K];
    __syncthreads();

    // ---- Phase D: attention over 110 memory_values slots ----
    const float* MV = mvals + (size_t)r * C_N * 64;
    {
        int warp = tid >> 5, lane = tid & 31;
        for (int s = warp; s < C_SLOTS; s += 8) {
            const float* v = MV + (size_t)s_slot[s] * 64;
            float p = fmaf(v[lane], s_q[lane], v[lane + 32] * s_q[lane + 32]);
#pragma unroll
            for (int o = 16; o > 0; o >>= 1) p += __shfl_down_sync(0xffffffffu, p, o);
            if (lane == 0) s_sc[s] = p * 0.125f;
        }
    }
    __syncthreads();
    if (tid == 0) {
        float m = -FLT_MAX;
        for (int s = 0; s < C_SLOTS; s++) m = fmaxf(m, s_sc[s]);
        s_mz[0] = m;
    }
    __syncthreads();
    if (tid < C_SLOTS) s_sc[tid] = expf(s_sc[tid] - s_mz[0]);
    __syncthreads();
    if (tid == 0) {
        float z = 0.0f;
        for (int s = 0; s < C_SLOTS; s++) z += s_sc[s];
        s_mz[1] = 1.0f / z;
    }
    __syncthreads();
    {
        int g = tid >> 6, d = tid & 63;
        float p = 0.0f;
        for (int s = g; s < C_SLOTS; s += 4) p = fmaf(s_sc[s], MV[(size_t)s_slot[s] * 64 + d], p);
        s_red[tid] = p;
        __syncthreads();
        if (tid < 64) {
            float o = (s_red[tid] + s_red[tid + 64] + s_red[tid + 128] + s_red[tid + 192]) * s_mz[1];
            g_attd[(size_t)row * C_H + r * 64 + tid] = o;
        }
    }
}

// ---------------- layernorm + output + loss write ----------------
__global__ __launch_bounds__(256) void k_ln(
    const float* __restrict__ lng, const float* __restrict__ lnb, float* __restrict__ out)
{
    const int row = blockIdx.x;
    const int tid = threadIdx.x;
    __shared__ float s_red[256];
    __shared__ float s_mu, s_rs;
    const float* h = g_h2 + (size_t)row * C_H;
    float h0 = h[tid], h1 = h[tid + 256], h2 = h[tid + 512];
    s_red[tid] = h0 + h1 + h2;
    __syncthreads();
    for (int s = 128; s > 0; s >>= 1) { if (tid < s) s_red[tid] += s_red[tid + s]; __syncthreads(); }
    if (tid == 0) s_mu = s_red[0] * (1.0f / C_H);
    __syncthreads();
    float mu = s_mu;
    float d0 = h0 - mu, d1 = h1 - mu, d2 = h2 - mu;
    s_red[tid] = d0 * d0 + d1 * d1 + d2 * d2;
    __syncthreads();
    for (int s = 128; s > 0; s >>= 1) { if (tid < s) s_red[tid] += s_red[tid + s]; __syncthreads(); }
    if (tid == 0) s_rs = rsqrtf(s_red[0] * (1.0f / C_H) + 1e-5f);
    __syncthreads();
    float rs = s_rs;
    out[(size_t)row * C_H + tid]       = d0 * rs * lng[tid]       + lnb[tid];
    out[(size_t)row * C_H + tid + 256] = d1 * rs * lng[tid + 256] + lnb[tid + 256];
    out[(size_t)row * C_H + tid + 512] = d2 * rs * lng[tid + 512] + lnb[tid + 512];
    if (row == 0 && tid == 0) out[(size_t)C_BE * C_H] = g_loss;
}

// ---------------- host launch ----------------
extern "C" void kernel_launch(void* const* d_in, const int* in_sizes, int n_in,
                              void* d_out, int out_size)
{
    (void)in_sizes; (void)n_in; (void)out_size;
    const float* elem_hiddens = (const float*)d_in[0];
    const float* e2e          = (const float*)d_in[1];
    const float* Wq_idx       = (const float*)d_in[2];
    const float* bq_idx       = (const float*)d_in[3];
    const float* key0         = (const float*)d_in[4];
    const float* key1         = (const float*)d_in[5];
    const float* key2         = (const float*)d_in[6];
    const float* key3         = (const float*)d_in[7];
    // d_in[8] = memory_keys: dead code in reference (attention scores against VALUES)
    const float* mvals        = (const float*)d_in[9];
    const float* wweights     = (const float*)d_in[10];
    const float* Wq_mha       = (const float*)d_in[11];
    const float* bq_mha       = (const float*)d_in[12];
    const float* W1           = (const float*)d_in[13];
    const float* b1           = (const float*)d_in[14];
    const float* W2           = (const float*)d_in[15];
    const float* b2           = (const float*)d_in[16];
    const float* ln_g         = (const float*)d_in[17];
    const float* ln_b         = (const float*)d_in[18];
    const int*   wedges       = (const int*)d_in[19];
    float* out = (float*)d_out;

    float *p_qidx, *p_qh, *p_attd, *p_h1, *p_h2;
    cudaGetSymbolAddress((void**)&p_qidx, g_qidx);
    cudaGetSymbolAddress((void**)&p_qh,   g_qh);
    cudaGetSymbolAddress((void**)&p_attd, g_attd);
    cudaGetSymbolAddress((void**)&p_h1,   g_h1);
    cudaGetSymbolAddress((void**)&p_h2,   g_h2);

    k_init<<<1, 1>>>();
    // indexer queries: (512x768) @ (768x256) + bq_idx
    sgemm_bias<<<dim3(256 / 64, C_BE / 64), 256>>>(elem_hiddens, Wq_idx, bq_idx, p_qidx, C_BE, 256, C_H, 0);
    // mha queries: (512x768) @ (768x768) + bq_mha
    sgemm_bias<<<dim3(C_H / 64, C_BE / 64), 256>>>(elem_hiddens, Wq_mha, bq_mha, p_qh, C_BE, C_H, C_H, 0);
    // product-key top-k retrieval
    k_indexer<<<C_BE, 128>>>(key0, key1, key2, key3);
    // fused sparse block per (row, r)
    k_main<<<dim3(C_BE, C_R), 256>>>(wedges, wweights, mvals, e2e);
    // FFN
    sgemm_bias<<<dim3(C_INTER / 64, C_BE / 64), 256>>>(p_attd, W1, b1, p_h1, C_BE, C_INTER, C_H, 1);
    sgemm_bias<<<dim3(C_H / 64, C_BE / 64), 256>>>(p_h1, W2, b2, p_h2, C_BE, C_H, C_INTER, 0);
    // layernorm + write output + loss scalar
    k_ln<<<C_BE, 256>>>(ln_g, ln_b, out);
}